// round 3
// baseline (speedup 1.0000x reference)
#include <cuda_runtime.h>

// CausalRevIN: B=16, T=8192, C=128, fp32.
// Single-pass segment scan, warp-parallel decoupled lookback (2 chained rounds).

#define BB 16
#define TT 8192
#define CC 128
#define SS 128                  // segments per series
#define LL 64                   // timesteps per segment (TT/SS)
#define NSEG (BB * SS)          // 2048 tiles

#define STD_MIN 1e-5f
#define MAX_VAL 100.0f

// Lookback state (per tile x channel).
__device__ float g_aggA_nm[NSEG * CC];
__device__ float g_aggA_x [NSEG * CC];
__device__ float g_incA_nm[NSEG * CC];
__device__ float g_incA_x [NSEG * CC];
__device__ float g_aggC   [NSEG * CC];
__device__ float g_incC   [NSEG * CC];
__device__ int   g_stateA [NSEG];
__device__ int   g_stateC [NSEG];
__device__ int   g_ticket;

__global__ void k_init() {
    int i = blockIdx.x * blockDim.x + threadIdx.x;
    if (i < NSEG) { g_stateA[i] = 0; g_stateC[i] = 0; }
    if (i == 0) g_ticket = 0;
}

__global__ void __launch_bounds__(128) k_main(const float* __restrict__ x,
                                              const float* __restrict__ m,
                                              float* __restrict__ out) {
    __shared__ float x_tile[LL * CC];      // 32 KB
    __shared__ int sh_tile;
    __shared__ int sh_lane_inc;

    const int tid = threadIdx.x;
    if (tid == 0) sh_tile = atomicAdd(&g_ticket, 1);
    __syncthreads();
    const int tile = sh_tile;
    const int b   = tile >> 7;
    const int seg = tile & (SS - 1);
    const int c   = tid;
    const int bbase = b << 7;              // first tile of this series
    const size_t gbase = ((size_t)b * TT + (size_t)seg * LL) * CC + c;
    const int idx = tile * CC + c;

    // ---------------- Phase 1: load tile, local sums ----------------
    unsigned long long nmbits = 0ULL;
    float snm = 0.f, sx = 0.f;
    #pragma unroll 16
    for (int t = 0; t < LL; t++) {
        float xv = x[gbase + (size_t)t * CC];
        float mv = m[gbase + (size_t)t * CC];
        x_tile[t * CC + c] = xv;
        sx += xv;
        if (mv == 0.0f) { nmbits |= (1ULL << t); snm += 1.0f; }
    }

    // Publish aggregate A (flag 1) BEFORE any lookback -> no circular waits.
    float excl_nm = 0.f, excl_x = 0.f;
    if (seg != 0) {
        g_aggA_nm[idx] = snm;
        g_aggA_x [idx] = sx;
        __threadfence();
        __syncthreads();
        if (tid == 0) atomicExch(&g_stateA[tile], 1);

        // -------- Warp-parallel lookback A --------
        int p_end = seg;                       // window = [p_end-cnt, p_end)
        for (;;) {
            int cnt = p_end < 32 ? p_end : 32;
            if (tid < 32) {
                int s = 2;
                if (tid < cnt) {
                    int pp = bbase + (p_end - 1 - tid);
                    do { s = atomicAdd(&g_stateA[pp], 0); } while (s == 0);
                }
                unsigned incmask = __ballot_sync(0xffffffffu, (s == 2) && (tid < cnt));
                if (tid == 0) {
                    __threadfence();
                    sh_lane_inc = incmask ? (__ffs(incmask) - 1) : -1;
                }
            }
            __syncthreads();
            int lane_inc = sh_lane_inc;
            int nagg = (lane_inc >= 0) ? lane_inc : cnt;
            for (int l = 0; l < nagg; l++) {
                int pidx = (bbase + p_end - 1 - l) * CC + c;
                excl_nm += __ldcg(&g_aggA_nm[pidx]);
                excl_x  += __ldcg(&g_aggA_x [pidx]);
            }
            if (lane_inc >= 0) {
                int pidx = (bbase + p_end - 1 - lane_inc) * CC + c;
                excl_nm += __ldcg(&g_incA_nm[pidx]);
                excl_x  += __ldcg(&g_incA_x [pidx]);
                break;                         // uniform across block
            }
            p_end -= cnt;
            __syncthreads();                   // guard sh_lane_inc reuse
        }
    }
    // Publish inclusive A (flag 2).
    g_incA_nm[idx] = excl_nm + snm;
    g_incA_x [idx] = excl_x  + sx;
    __threadfence();
    __syncthreads();
    if (tid == 0) atomicExch(&g_stateA[tile], 2);

    // ---------------- Phase 2: local sum of ((x-mean)*nm)^2 ----------------
    float cn = excl_nm, cx = excl_x, lss = 0.f;
    #pragma unroll 16
    for (int t = 0; t < LL; t++) {
        float xv = x_tile[t * CC + c];
        float nm = (float)((nmbits >> t) & 1ULL);
        cn += nm;
        cx += xv;
        float n = (cn == 0.f) ? 1.f : cn;
        float mean = __fdividef(cx, n);
        float d = (xv - mean) * nm;
        lss += d * d;
    }

    // Publish aggregate C, then lookback C.
    float excl_s = 0.f;
    if (seg != 0) {
        g_aggC[idx] = lss;
        __threadfence();
        __syncthreads();
        if (tid == 0) atomicExch(&g_stateC[tile], 1);

        int p_end = seg;
        for (;;) {
            int cnt = p_end < 32 ? p_end : 32;
            if (tid < 32) {
                int s = 2;
                if (tid < cnt) {
                    int pp = bbase + (p_end - 1 - tid);
                    do { s = atomicAdd(&g_stateC[pp], 0); } while (s == 0);
                }
                unsigned incmask = __ballot_sync(0xffffffffu, (s == 2) && (tid < cnt));
                if (tid == 0) {
                    __threadfence();
                    sh_lane_inc = incmask ? (__ffs(incmask) - 1) : -1;
                }
            }
            __syncthreads();
            int lane_inc = sh_lane_inc;
            int nagg = (lane_inc >= 0) ? lane_inc : cnt;
            for (int l = 0; l < nagg; l++) {
                int pidx = (bbase + p_end - 1 - l) * CC + c;
                excl_s += __ldcg(&g_aggC[pidx]);
            }
            if (lane_inc >= 0) {
                int pidx = (bbase + p_end - 1 - lane_inc) * CC + c;
                excl_s += __ldcg(&g_incC[pidx]);
                break;
            }
            p_end -= cnt;
            __syncthreads();
        }
    }
    g_incC[idx] = excl_s + lss;
    __threadfence();
    __syncthreads();
    if (tid == 0) atomicExch(&g_stateC[tile], 2);

    // ---------------- Phase 3: normalize + clip, write out ----------------
    cn = excl_nm; cx = excl_x;
    float cs = excl_s;
    #pragma unroll 8
    for (int t = 0; t < LL; t++) {
        float xv = x_tile[t * CC + c];
        float nm = (float)((nmbits >> t) & 1ULL);
        cn += nm;
        cx += xv;
        float n = (cn == 0.f) ? 1.f : cn;
        float mean = __fdividef(cx, n);
        float d = (xv - mean) * nm;
        cs += d * d;
        float stdv = sqrtf(__fdividef(cs, n));
        float num = xv - mean;
        float res = (stdv > STD_MIN) ? __fdividef(num, stdv) : num;
        res = fminf(fmaxf(res, -MAX_VAL), MAX_VAL);
        out[gbase + (size_t)t * CC] = res;
    }
}

extern "C" void kernel_launch(void* const* d_in, const int* in_sizes, int n_in,
                              void* d_out, int out_size) {
    const float* x = (const float*)d_in[0];
    const float* m = (const float*)d_in[1];
    float* out = (float*)d_out;

    k_init<<<(NSEG + 255) / 256, 256>>>();
    k_main<<<NSEG, 128>>>(x, m, out);
}

// round 4
// speedup vs baseline: 1.2486x; 1.2486x over previous
#include <cuda_runtime.h>

// CausalRevIN: B=16, T=8192, C=128, fp32.
// Single-pass scan. Tile = 256 timesteps (4 warps x 64t), thread = 4 channels (float4).
// 512 CTAs -> fully resident; single-window warp-parallel decoupled lookback.

#define BB 16
#define TT 8192
#define CC 128
#define TILE_T 256
#define SPW 64                  // timesteps per warp
#define SPB 32                  // tiles per series
#define NTILE (BB * SPB)        // 512

#define STD_MIN 1e-5f
#define MAX_VAL 100.0f

__device__ float4 g_aggA_nm[NTILE * 32];
__device__ float4 g_aggA_x [NTILE * 32];
__device__ float4 g_incA_nm[NTILE * 32];
__device__ float4 g_incA_x [NTILE * 32];
__device__ float4 g_aggC   [NTILE * 32];
__device__ float4 g_incC   [NTILE * 32];
__device__ int    g_stateA [NTILE];
__device__ int    g_stateC [NTILE];
__device__ int    g_ticket;

__global__ void k_init() {
    int i = blockIdx.x * blockDim.x + threadIdx.x;
    if (i < NTILE) { g_stateA[i] = 0; g_stateC[i] = 0; }
    if (i == 0) g_ticket = 0;
}

__device__ __forceinline__ void f4add(float4& a, const float4 b) {
    a.x += b.x; a.y += b.y; a.z += b.z; a.w += b.w;
}

__global__ void __launch_bounds__(128) k_main(const float* __restrict__ x,
                                              const float* __restrict__ m,
                                              float* __restrict__ out) {
    __shared__ float4 s_a[128];
    __shared__ float4 s_b[128];
    __shared__ int sh_tile;

    const int tid = threadIdx.x;
    if (tid == 0) sh_tile = atomicAdd(&g_ticket, 1);
    __syncthreads();
    const int tile = sh_tile;
    const int b   = tile >> 5;
    const int seg = tile & 31;
    const int w   = tid >> 5;
    const int l   = tid & 31;
    const int bbase = b << 5;

    const float4* x4 = (const float4*)x;
    const float4* m4 = (const float4*)m;
    float4* o4 = (float4*)out;
    const size_t rowbase = ((size_t)b * TT + (size_t)seg * TILE_T + (size_t)w * SPW) * 32 + l;

    // ================= Phase 1: load, local sums, pack mask bits =================
    float4 snm = make_float4(0.f, 0.f, 0.f, 0.f);
    float4 sx  = make_float4(0.f, 0.f, 0.f, 0.f);
    unsigned long long nb0 = 0, nb1 = 0, nb2 = 0, nb3 = 0;
    #pragma unroll 8
    for (int t = 0; t < SPW; t++) {
        float4 xv = x4[rowbase + (size_t)t * 32];
        float4 mv = __ldcs(&m4[rowbase + (size_t)t * 32]);
        f4add(sx, xv);
        if (mv.x == 0.f) { nb0 |= 1ULL << t; snm.x += 1.f; }
        if (mv.y == 0.f) { nb1 |= 1ULL << t; snm.y += 1.f; }
        if (mv.z == 0.f) { nb2 |= 1ULL << t; snm.z += 1.f; }
        if (mv.w == 0.f) { nb3 |= 1ULL << t; snm.w += 1.f; }
    }
    s_a[tid] = snm; s_b[tid] = sx;
    __syncthreads();

    // warp-exclusive prefix (over warps, same lane)
    float4 we_nm = make_float4(0.f, 0.f, 0.f, 0.f);
    float4 we_x  = make_float4(0.f, 0.f, 0.f, 0.f);
    for (int ww = 0; ww < w; ww++) { f4add(we_nm, s_a[ww * 32 + l]); f4add(we_x, s_b[ww * 32 + l]); }
    // warp 0 also needs CTA totals
    float4 tot_nm, tot_x;
    if (w == 0) {
        tot_nm = s_a[l];       tot_x = s_b[l];
        f4add(tot_nm, s_a[32 + l]);  f4add(tot_x, s_b[32 + l]);
        f4add(tot_nm, s_a[64 + l]);  f4add(tot_x, s_b[64 + l]);
        f4add(tot_nm, s_a[96 + l]);  f4add(tot_x, s_b[96 + l]);
    }
    __syncthreads();           // all smem reads done; warp0 may overwrite

    // ================= Lookback A (warp 0), publish inclusive =================
    if (w == 0) {
        float4 ex_nm = make_float4(0.f, 0.f, 0.f, 0.f);
        float4 ex_x  = make_float4(0.f, 0.f, 0.f, 0.f);
        if (seg != 0) {
            g_aggA_nm[tile * 32 + l] = snm;   // note: warp0's own snm is NOT the CTA agg
            g_aggA_x [tile * 32 + l] = tot_x; // placeholder, fixed below
        }
        // (correct publish): aggregate = CTA totals
        if (seg != 0) {
            g_aggA_nm[tile * 32 + l] = tot_nm;
            g_aggA_x [tile * 32 + l] = tot_x;
            __threadfence();
            __syncwarp();
            if (l == 0) atomicExch(&g_stateA[tile], 1);

            int s = 0;
            if (l < seg) {
                int pp = bbase + seg - 1 - l;
                do { s = atomicAdd(&g_stateA[pp], 0); } while (s == 0);
            }
            unsigned incmask = __ballot_sync(0xffffffffu, s == 2);
            __threadfence();
            int lane_inc = __ffs(incmask) - 1;   // guaranteed: tile0 of series has flag 2
            for (int j = 0; j < lane_inc; j++) {
                int pidx = (bbase + seg - 1 - j) * 32 + l;
                f4add(ex_nm, __ldcg(&g_aggA_nm[pidx]));
                f4add(ex_x,  __ldcg(&g_aggA_x [pidx]));
            }
            {
                int pidx = (bbase + seg - 1 - lane_inc) * 32 + l;
                f4add(ex_nm, __ldcg(&g_incA_nm[pidx]));
                f4add(ex_x,  __ldcg(&g_incA_x [pidx]));
            }
        }
        // publish inclusive
        float4 in_nm = ex_nm, in_x = ex_x;
        f4add(in_nm, tot_nm); f4add(in_x, tot_x);
        g_incA_nm[tile * 32 + l] = in_nm;
        g_incA_x [tile * 32 + l] = in_x;
        __threadfence();
        __syncwarp();
        if (l == 0) atomicExch(&g_stateA[tile], 2);
        s_a[l] = ex_nm; s_b[l] = ex_x;
    }
    __syncthreads();
    float4 base_n = s_a[l], base_x = s_b[l];
    f4add(base_n, we_nm); f4add(base_x, we_x);

    // ================= Phase 2: local sum of ((x-mean)*nm)^2 =================
    float4 cn = base_n, cx = base_x;
    float4 lss = make_float4(0.f, 0.f, 0.f, 0.f);
    #pragma unroll 8
    for (int t = 0; t < SPW; t++) {
        float4 xv = x4[rowbase + (size_t)t * 32];
        #define STEP2(k, bits)                                            \
        {                                                                 \
            float nm = ((bits >> t) & 1ULL) ? 1.f : 0.f;                  \
            cn.k += nm; cx.k += xv.k;                                     \
            float n = (cn.k == 0.f) ? 1.f : cn.k;                         \
            float mean = cx.k * __fdividef(1.f, n);                       \
            float d = (xv.k - mean) * nm;                                 \
            lss.k += d * d;                                               \
        }
        STEP2(x, nb0) STEP2(y, nb1) STEP2(z, nb2) STEP2(w, nb3)
        #undef STEP2
    }
    __syncthreads();           // protect s_a reuse
    s_a[tid] = lss;
    __syncthreads();
    float4 we_s = make_float4(0.f, 0.f, 0.f, 0.f);
    for (int ww = 0; ww < w; ww++) f4add(we_s, s_a[ww * 32 + l]);
    float4 tot_s;
    if (w == 0) {
        tot_s = s_a[l];
        f4add(tot_s, s_a[32 + l]); f4add(tot_s, s_a[64 + l]); f4add(tot_s, s_a[96 + l]);
    }
    __syncthreads();

    // ================= Lookback C (warp 0) =================
    if (w == 0) {
        float4 ex_s = make_float4(0.f, 0.f, 0.f, 0.f);
        if (seg != 0) {
            g_aggC[tile * 32 + l] = tot_s;
            __threadfence();
            __syncwarp();
            if (l == 0) atomicExch(&g_stateC[tile], 1);

            int s = 0;
            if (l < seg) {
                int pp = bbase + seg - 1 - l;
                do { s = atomicAdd(&g_stateC[pp], 0); } while (s == 0);
            }
            unsigned incmask = __ballot_sync(0xffffffffu, s == 2);
            __threadfence();
            int lane_inc = __ffs(incmask) - 1;
            for (int j = 0; j < lane_inc; j++)
                f4add(ex_s, __ldcg(&g_aggC[(bbase + seg - 1 - j) * 32 + l]));
            f4add(ex_s, __ldcg(&g_incC[(bbase + seg - 1 - lane_inc) * 32 + l]));
        }
        float4 in_s = ex_s; f4add(in_s, tot_s);
        g_incC[tile * 32 + l] = in_s;
        __threadfence();
        __syncwarp();
        if (l == 0) atomicExch(&g_stateC[tile], 2);
        s_a[l] = ex_s;
    }
    __syncthreads();
    float4 base_s = s_a[l];
    f4add(base_s, we_s);

    // ================= Phase 3: normalize + clip, write out =================
    cn = base_n; cx = base_x;
    float4 cs = base_s;
    #pragma unroll 8
    for (int t = 0; t < SPW; t++) {
        float4 xv = __ldcs(&x4[rowbase + (size_t)t * 32]);
        float4 ov;
        #define STEP3(k, bits)                                            \
        {                                                                 \
            float nm = ((bits >> t) & 1ULL) ? 1.f : 0.f;                  \
            cn.k += nm; cx.k += xv.k;                                     \
            float n = (cn.k == 0.f) ? 1.f : cn.k;                         \
            float rn = __fdividef(1.f, n);                                \
            float mean = cx.k * rn;                                       \
            float num = xv.k - mean;                                      \
            float d = num * nm;                                           \
            cs.k += d * d;                                                \
            float var = cs.k * rn;                                        \
            float res = (var > STD_MIN * STD_MIN) ? num * rsqrtf(var) : num; \
            ov.k = fminf(fmaxf(res, -MAX_VAL), MAX_VAL);                  \
        }
        STEP3(x, nb0) STEP3(y, nb1) STEP3(z, nb2) STEP3(w, nb3)
        #undef STEP3
        __stcs(&o4[rowbase + (size_t)t * 32], ov);
    }
}

extern "C" void kernel_launch(void* const* d_in, const int* in_sizes, int n_in,
                              void* d_out, int out_size) {
    const float* x = (const float*)d_in[0];
    const float* m = (const float*)d_in[1];
    float* out = (float*)d_out;

    k_init<<<(NTILE + 255) / 256, 256>>>();
    k_main<<<NTILE, 128>>>(x, m, out);
}

// round 5
// speedup vs baseline: 1.3294x; 1.0647x over previous
#include <cuda_runtime.h>

// CausalRevIN: B=16, T=8192, C=128, fp32.
// Single-pass scan. Tile = 128 timesteps (4 warps x 32 t), thread = 4 channels (float4).
// 1024 CTAs, 7 CTAs/SM -> fully resident single wave; windowed warp-parallel lookback.

#define BB 16
#define TT 8192
#define TILE_T 128
#define SPW 32                  // timesteps per warp
#define SPB 64                  // tiles per series
#define NTILE (BB * SPB)        // 1024

#define STD_MIN 1e-5f
#define MAX_VAL 100.0f

__device__ float4 g_aggA_nm[NTILE * 32];
__device__ float4 g_aggA_x [NTILE * 32];
__device__ float4 g_incA_nm[NTILE * 32];
__device__ float4 g_incA_x [NTILE * 32];
__device__ float4 g_aggC   [NTILE * 32];
__device__ float4 g_incC   [NTILE * 32];
__device__ int    g_stateA [NTILE];
__device__ int    g_stateC [NTILE];
__device__ int    g_ticket;

__global__ void k_init() {
    int i = blockIdx.x * blockDim.x + threadIdx.x;
    if (i < NTILE) { g_stateA[i] = 0; g_stateC[i] = 0; }
    if (i == 0) g_ticket = 0;
}

__device__ __forceinline__ void f4add(float4& a, const float4 b) {
    a.x += b.x; a.y += b.y; a.z += b.z; a.w += b.w;
}

__global__ void __launch_bounds__(128, 7) k_main(const float* __restrict__ x,
                                                 const float* __restrict__ m,
                                                 float* __restrict__ out) {
    __shared__ float4 s_a[128];
    __shared__ float4 s_b[128];
    __shared__ int sh_tile;

    const int tid = threadIdx.x;
    if (tid == 0) sh_tile = atomicAdd(&g_ticket, 1);
    __syncthreads();
    const int tile = sh_tile;
    const int b   = tile >> 6;             // tile / SPB
    const int seg = tile & (SPB - 1);
    const int w   = tid >> 5;
    const int l   = tid & 31;
    const int bbase = b << 6;              // first tile of this series

    const float4* __restrict__ x4 = (const float4*)x;
    const float4* __restrict__ m4 = (const float4*)m;
    float4* __restrict__ o4 = (float4*)out;
    // 32-bit indexing: max index = 16*8192*32 = 4.19M
    const int rowbase = (b * TT + seg * TILE_T + w * SPW) * 32 + l;

    // ================= Phase 1: load, local sums, pack mask bits =================
    float4 snm = make_float4(0.f, 0.f, 0.f, 0.f);
    float4 sx  = make_float4(0.f, 0.f, 0.f, 0.f);
    unsigned nb0 = 0, nb1 = 0, nb2 = 0, nb3 = 0;
    #pragma unroll 8
    for (int t = 0; t < SPW; t++) {
        float4 xv = x4[rowbase + t * 32];
        float4 mv = __ldcs(&m4[rowbase + t * 32]);
        f4add(sx, xv);
        if (mv.x == 0.f) { nb0 |= 1u << t; snm.x += 1.f; }
        if (mv.y == 0.f) { nb1 |= 1u << t; snm.y += 1.f; }
        if (mv.z == 0.f) { nb2 |= 1u << t; snm.z += 1.f; }
        if (mv.w == 0.f) { nb3 |= 1u << t; snm.w += 1.f; }
    }
    s_a[tid] = snm; s_b[tid] = sx;
    __syncthreads();

    // exclusive prefix over warps (same lane) + CTA totals for warp 0
    float4 we_nm = make_float4(0.f, 0.f, 0.f, 0.f);
    float4 we_x  = make_float4(0.f, 0.f, 0.f, 0.f);
    for (int ww = 0; ww < w; ww++) { f4add(we_nm, s_a[ww * 32 + l]); f4add(we_x, s_b[ww * 32 + l]); }
    float4 tot_nm, tot_x;
    if (w == 0) {
        tot_nm = s_a[l];            tot_x = s_b[l];
        f4add(tot_nm, s_a[32 + l]); f4add(tot_x, s_b[32 + l]);
        f4add(tot_nm, s_a[64 + l]); f4add(tot_x, s_b[64 + l]);
        f4add(tot_nm, s_a[96 + l]); f4add(tot_x, s_b[96 + l]);
    }
    __syncthreads();

    // ================= Lookback A (warp 0) =================
    if (w == 0) {
        float4 ex_nm = make_float4(0.f, 0.f, 0.f, 0.f);
        float4 ex_x  = make_float4(0.f, 0.f, 0.f, 0.f);
        if (seg != 0) {
            g_aggA_nm[tile * 32 + l] = tot_nm;
            g_aggA_x [tile * 32 + l] = tot_x;
            __threadfence();
            __syncwarp();
            if (l == 0) atomicExch(&g_stateA[tile], 1);

            int p_end = seg;
            for (;;) {
                int cnt = p_end < 32 ? p_end : 32;
                int s = 2;
                if (l < cnt) {
                    int pp = bbase + p_end - 1 - l;
                    do { s = atomicAdd(&g_stateA[pp], 0); } while (s == 0);
                }
                unsigned incmask = __ballot_sync(0xffffffffu, (s == 2) && (l < cnt));
                __threadfence();
                int li = incmask ? (__ffs(incmask) - 1) : -1;
                int nagg = (li >= 0) ? li : cnt;
                for (int j = 0; j < nagg; j++) {
                    int pidx = (bbase + p_end - 1 - j) * 32 + l;
                    f4add(ex_nm, __ldcg(&g_aggA_nm[pidx]));
                    f4add(ex_x,  __ldcg(&g_aggA_x [pidx]));
                }
                if (li >= 0) {
                    int pidx = (bbase + p_end - 1 - li) * 32 + l;
                    f4add(ex_nm, __ldcg(&g_incA_nm[pidx]));
                    f4add(ex_x,  __ldcg(&g_incA_x [pidx]));
                    break;
                }
                p_end -= cnt;
            }
        }
        float4 in_nm = ex_nm, in_x = ex_x;
        f4add(in_nm, tot_nm); f4add(in_x, tot_x);
        g_incA_nm[tile * 32 + l] = in_nm;
        g_incA_x [tile * 32 + l] = in_x;
        __threadfence();
        __syncwarp();
        if (l == 0) atomicExch(&g_stateA[tile], 2);
        s_a[l] = ex_nm; s_b[l] = ex_x;
    }
    __syncthreads();
    float4 base_n = s_a[l], base_x = s_b[l];
    f4add(base_n, we_nm); f4add(base_x, we_x);

    // ================= Phase 2: local sum of ((x-mean)*nm)^2 =================
    float4 cn = base_n, cx = base_x;
    float4 lss = make_float4(0.f, 0.f, 0.f, 0.f);
    #pragma unroll 8
    for (int t = 0; t < SPW; t++) {
        float4 xv = x4[rowbase + t * 32];
        #define STEP2(k, bits)                                            \
        {                                                                 \
            float nm = ((bits >> t) & 1u) ? 1.f : 0.f;                    \
            cn.k += nm; cx.k += xv.k;                                     \
            float n = (cn.k == 0.f) ? 1.f : cn.k;                         \
            float mean = cx.k * __fdividef(1.f, n);                       \
            float d = (xv.k - mean) * nm;                                 \
            lss.k += d * d;                                               \
        }
        STEP2(x, nb0) STEP2(y, nb1) STEP2(z, nb2) STEP2(w, nb3)
        #undef STEP2
    }
    __syncthreads();
    s_a[tid] = lss;
    __syncthreads();
    float4 we_s = make_float4(0.f, 0.f, 0.f, 0.f);
    for (int ww = 0; ww < w; ww++) f4add(we_s, s_a[ww * 32 + l]);
    float4 tot_s;
    if (w == 0) {
        tot_s = s_a[l];
        f4add(tot_s, s_a[32 + l]); f4add(tot_s, s_a[64 + l]); f4add(tot_s, s_a[96 + l]);
    }
    __syncthreads();

    // ================= Lookback C (warp 0) =================
    if (w == 0) {
        float4 ex_s = make_float4(0.f, 0.f, 0.f, 0.f);
        if (seg != 0) {
            g_aggC[tile * 32 + l] = tot_s;
            __threadfence();
            __syncwarp();
            if (l == 0) atomicExch(&g_stateC[tile], 1);

            int p_end = seg;
            for (;;) {
                int cnt = p_end < 32 ? p_end : 32;
                int s = 2;
                if (l < cnt) {
                    int pp = bbase + p_end - 1 - l;
                    do { s = atomicAdd(&g_stateC[pp], 0); } while (s == 0);
                }
                unsigned incmask = __ballot_sync(0xffffffffu, (s == 2) && (l < cnt));
                __threadfence();
                int li = incmask ? (__ffs(incmask) - 1) : -1;
                int nagg = (li >= 0) ? li : cnt;
                for (int j = 0; j < nagg; j++)
                    f4add(ex_s, __ldcg(&g_aggC[(bbase + p_end - 1 - j) * 32 + l]));
                if (li >= 0) {
                    f4add(ex_s, __ldcg(&g_incC[(bbase + p_end - 1 - li) * 32 + l]));
                    break;
                }
                p_end -= cnt;
            }
        }
        float4 in_s = ex_s; f4add(in_s, tot_s);
        g_incC[tile * 32 + l] = in_s;
        __threadfence();
        __syncwarp();
        if (l == 0) atomicExch(&g_stateC[tile], 2);
        s_a[l] = ex_s;
    }
    __syncthreads();
    float4 base_s = s_a[l];
    f4add(base_s, we_s);

    // ================= Phase 3: normalize + clip, write out =================
    cn = base_n; cx = base_x;
    float4 cs = base_s;
    #pragma unroll 8
    for (int t = 0; t < SPW; t++) {
        float4 xv = __ldcs(&x4[rowbase + t * 32]);
        float4 ov;
        #define STEP3(k, bits)                                            \
        {                                                                 \
            float nm = ((bits >> t) & 1u) ? 1.f : 0.f;                    \
            cn.k += nm; cx.k += xv.k;                                     \
            float n = (cn.k == 0.f) ? 1.f : cn.k;                         \
            float rn = __fdividef(1.f, n);                                \
            float mean = cx.k * rn;                                       \
            float num = xv.k - mean;                                      \
            float d = num * nm;                                           \
            cs.k += d * d;                                                \
            float var = cs.k * rn;                                        \
            float res = (var > STD_MIN * STD_MIN) ? num * rsqrtf(var) : num; \
            ov.k = fminf(fmaxf(res, -MAX_VAL), MAX_VAL);                  \
        }
        STEP3(x, nb0) STEP3(y, nb1) STEP3(z, nb2) STEP3(w, nb3)
        #undef STEP3
        __stcs(&o4[rowbase + t * 32], ov);
    }
}

extern "C" void kernel_launch(void* const* d_in, const int* in_sizes, int n_in,
                              void* d_out, int out_size) {
    const float* x = (const float*)d_in[0];
    const float* m = (const float*)d_in[1];
    float* out = (float*)d_out;

    k_init<<<(NTILE + 255) / 256, 256>>>();
    k_main<<<NTILE, 128>>>(x, m, out);
}